// round 1
// baseline (speedup 1.0000x reference)
#include <cuda_runtime.h>

// Sliding-window gated attention (W=32, D=64), fp32.
// out[b,s,h,:] = sum_{w=0..31} [ (q_s . k_j) * scale * sigmoid(a_j * b_s) * (j>=0) ] * v_j,
//   j = s - 31 + w.

#define FULL_MASK 0xffffffffu

constexpr int B_  = 2;
constexpr int S_  = 2048;
constexpr int H_  = 8;
constexpr int D_  = 64;
constexpr int W_  = 32;
constexpr int TS  = 64;             // queries per block tile
constexpr int ROWS = TS + W_ - 1;   // 95 k/v rows needed per tile
constexpr int STRIDE = 68;          // smem row stride in floats (conflict-free for our patterns)
constexpr float SCALE = 0.125f;     // 1/sqrt(64)

__global__ __launch_bounds__(256, 1)
void swa_gated_kernel(const float* __restrict__ qg,
                      const float* __restrict__ kg,
                      const float* __restrict__ vg,
                      const float* __restrict__ ag,
                      const float* __restrict__ bg,
                      float* __restrict__ outg)
{
    extern __shared__ float sm[];
    float* ks = sm;                         // ROWS * STRIDE
    float* vs = sm + ROWS * STRIDE;         // ROWS * STRIDE
    float* as = sm + 2 * ROWS * STRIDE;     // ROWS (+pad)

    const int s0  = blockIdx.x * TS;
    const int h   = blockIdx.y;
    const int bb  = blockIdx.z;
    const int tid = threadIdx.x;

    // Base offset of (bb, s=0, h, d=0) in the (B, S, H*D) tensors.
    const size_t headBase = (size_t)bb * S_ * (H_ * D_) + (size_t)h * D_;

    // ---- Stage K/V window rows into shared memory (zero-fill j<0) ----
    for (int idx = tid; idx < ROWS * 16; idx += 256) {
        const int r = idx >> 4;
        const int c = (idx & 15) << 2;      // float4 column
        const int j = s0 - (W_ - 1) + r;
        float4 kv = make_float4(0.f, 0.f, 0.f, 0.f);
        float4 vv = make_float4(0.f, 0.f, 0.f, 0.f);
        if (j >= 0) {
            const size_t off = headBase + (size_t)j * (H_ * D_) + c;
            kv = *(const float4*)(kg + off);
            vv = *(const float4*)(vg + off);
        }
        *(float4*)(ks + r * STRIDE + c) = kv;
        *(float4*)(vs + r * STRIDE + c) = vv;
    }
    for (int r = tid; r < ROWS; r += 256) {
        const int j = s0 - (W_ - 1) + r;
        as[r] = (j >= 0) ? ag[((size_t)bb * S_ + j) * H_ + h] : 0.f;
    }
    __syncthreads();

    const int warp = tid >> 5;
    const int lane = tid & 31;
    const int qbase = warp * 8;             // each warp owns 8 consecutive queries

    // Prefetch q rows (2 regs/lane/query) and gate b values for the group.
    float qa[8], qb[8], bv[8];
#pragma unroll
    for (int i = 0; i < 8; i++) {
        const int s = s0 + qbase + i;
        const float* qr = qg + headBase + (size_t)s * (H_ * D_);
        qa[i] = qr[lane];
        qb[i] = qr[lane + 32];
        bv[i] = bg[((size_t)bb * S_ + s) * H_ + h];
    }

#pragma unroll
    for (int i = 0; i < 8; i++) {
        const int qloc = qbase + i;
        const int s = s0 + qloc;

        // ---- Score phase: lane = window slot w, row r = qloc + lane ----
        const float* kr = ks + (qloc + lane) * STRIDE;
        float acc = 0.f;
#pragma unroll
        for (int dd = 0; dd < 64; dd += 4) {
            const float4 k4 = *(const float4*)(kr + dd);
            const float src = (dd < 32) ? qa[i] : qb[i];
            const float x0 = __shfl_sync(FULL_MASK, src, (dd + 0) & 31);
            const float x1 = __shfl_sync(FULL_MASK, src, (dd + 1) & 31);
            const float x2 = __shfl_sync(FULL_MASK, src, (dd + 2) & 31);
            const float x3 = __shfl_sync(FULL_MASK, src, (dd + 3) & 31);
            acc = fmaf(k4.x, x0, acc);
            acc = fmaf(k4.y, x1, acc);
            acc = fmaf(k4.z, x2, acc);
            acc = fmaf(k4.w, x3, acc);
        }

        const int j = s - (W_ - 1) + lane;
        const float gate = 1.f / (1.f + __expf(-as[qloc + lane] * bv[i]));
        const float wgt = (j >= 0) ? acc * SCALE * gate : 0.f;

        // ---- Output phase: lane = dim pair d = {2*lane, 2*lane+1} ----
        float o0 = 0.f, o1 = 0.f;
        const float* vb = vs + qloc * STRIDE + 2 * lane;
#pragma unroll
        for (int w = 0; w < 32; w++) {
            const float g = __shfl_sync(FULL_MASK, wgt, w);
            const float2 vv = *(const float2*)(vb + w * STRIDE);
            o0 = fmaf(g, vv.x, o0);
            o1 = fmaf(g, vv.y, o1);
        }
        float2* op = (float2*)(outg + headBase + (size_t)s * (H_ * D_) + 2 * lane);
        *op = make_float2(o0, o1);
    }
}

extern "C" void kernel_launch(void* const* d_in, const int* in_sizes, int n_in,
                              void* d_out, int out_size)
{
    const float* q = (const float*)d_in[0];
    const float* k = (const float*)d_in[1];
    const float* v = (const float*)d_in[2];
    const float* a = (const float*)d_in[3];
    const float* b = (const float*)d_in[4];
    float* out = (float*)d_out;

    const size_t smem = (size_t)(2 * ROWS * STRIDE + ROWS + 1) * sizeof(float); // ~52 KB
    cudaFuncSetAttribute(swa_gated_kernel,
                         cudaFuncAttributeMaxDynamicSharedMemorySize, (int)smem);

    dim3 grid(S_ / TS, H_, B_);
    swa_gated_kernel<<<grid, 256, smem>>>(q, k, v, a, b, out);
}

// round 2
// speedup vs baseline: 1.0344x; 1.0344x over previous
#include <cuda_runtime.h>

// Sliding-window gated attention (W=32, D=64), fp32, row-centric.
// out[b,s,h,:] = sum_w (q_s . k_j) * scale * sigmoid(a_j*b_s) * [j>=0] * v_j, j = s-31+w.

#define FULL_MASK 0xffffffffu

constexpr int B_  = 2;
constexpr int S_  = 2048;
constexpr int H_  = 8;
constexpr int D_  = 64;
constexpr int W_  = 32;
constexpr int TS  = 64;              // queries per block
constexpr int ROWS = TS + W_ - 1;    // 95 k/v rows per block
constexpr int STRIDE = 68;           // smem row stride (floats)
constexpr int QPW = 8;               // queries per warp
constexpr int RPW = QPW + W_ - 1;    // 39 rows per warp
constexpr float SCALE = 0.125f;

__global__ __launch_bounds__(256, 3)
void swa_gated2_kernel(const float* __restrict__ qg,
                       const float* __restrict__ kg,
                       const float* __restrict__ vg,
                       const float* __restrict__ ag,
                       const float* __restrict__ bg,
                       float* __restrict__ outg)
{
    extern __shared__ float sm[];
    float* ks = sm;                               // ROWS*STRIDE
    float* vs = sm + ROWS * STRIDE;               // ROWS*STRIDE
    float* as = sm + 2 * ROWS * STRIDE;           // ROWS (+1 pad)
    float* ws = as + ROWS + 1;                    // 8 warps * RPW * 8 weights

    const int s0  = blockIdx.x * TS;
    const int h   = blockIdx.y;
    const int bb  = blockIdx.z;
    const int tid = threadIdx.x;
    const size_t headBase = (size_t)bb * S_ * (H_ * D_) + (size_t)h * D_;

    // ---- Stage K/V rows (zero-fill j<0) ----
    for (int idx = tid; idx < ROWS * 16; idx += 256) {
        const int r = idx >> 4;
        const int c = (idx & 15) << 2;
        const int j = s0 - (W_ - 1) + r;
        float4 kv = make_float4(0.f, 0.f, 0.f, 0.f);
        float4 vv = make_float4(0.f, 0.f, 0.f, 0.f);
        if (j >= 0) {
            const size_t off = headBase + (size_t)j * (H_ * D_) + c;
            kv = *(const float4*)(kg + off);
            vv = *(const float4*)(vg + off);
        }
        *(float4*)(ks + r * STRIDE + c) = kv;
        *(float4*)(vs + r * STRIDE + c) = vv;
    }
    for (int r = tid; r < ROWS; r += 256) {
        const int j = s0 - (W_ - 1) + r;
        as[r] = (j >= 0) ? ag[((size_t)bb * S_ + j) * H_ + h] : 0.f;
    }
    __syncthreads();

    const int warp  = tid >> 5;
    const int lane  = tid & 31;
    const int qbase = warp * QPW;

    // q held lane = dim-pair: qx[i] = q[2*lane], qy[i] = q[2*lane+1]
    float qx[QPW], qy[QPW];
#pragma unroll
    for (int i = 0; i < QPW; i++) {
        const float2 q2 = *(const float2*)(qg + headBase
                            + (size_t)(s0 + qbase + i) * (H_ * D_) + 2 * lane);
        qx[i] = q2.x; qy[i] = q2.y;
    }

    // After the fold reduce, lane holds the score for query index myq.
    const int  myq = ((lane >> 4) & 1) * 4 + ((lane >> 3) & 1) * 2 + ((lane >> 2) & 1);
    const float bv = bg[((size_t)bb * S_ + (s0 + qbase + myq)) * H_ + h];
    const bool b4 = (lane & 16) != 0;
    const bool b3 = (lane & 8)  != 0;
    const bool b2 = (lane & 4)  != 0;

    float* wsw = ws + warp * (RPW * 8);

    // ---- Phase 1: each row read ONCE; 8 query dots via fold reduction ----
#pragma unroll 4
    for (int rr = 0; rr < RPW; rr++) {
        const int l = qbase + rr;
        const float2 k2 = *(const float2*)(ks + l * STRIDE + 2 * lane);

        float p[QPW];
#pragma unroll
        for (int i = 0; i < QPW; i++)
            p[i] = fmaf(qx[i], k2.x, qy[i] * k2.y);

        float k0[4];
#pragma unroll
        for (int i = 0; i < 4; i++) {
            const float keep = b4 ? p[i + 4] : p[i];
            const float send = b4 ? p[i]     : p[i + 4];
            k0[i] = keep + __shfl_xor_sync(FULL_MASK, send, 16);
        }
        float k1[2];
#pragma unroll
        for (int i = 0; i < 2; i++) {
            const float keep = b3 ? k0[i + 2] : k0[i];
            const float send = b3 ? k0[i]     : k0[i + 2];
            k1[i] = keep + __shfl_xor_sync(FULL_MASK, send, 8);
        }
        float s = (b2 ? k1[1] : k1[0])
                + __shfl_xor_sync(FULL_MASK, b2 ? k1[0] : k1[1], 4);
        s += __shfl_xor_sync(FULL_MASK, s, 2);
        s += __shfl_xor_sync(FULL_MASK, s, 1);

        const int w = rr - myq;                    // window slot for my query
        const int j = s0 - (W_ - 1) + l;
        const float gate = 1.f / (1.f + __expf(-as[l] * bv));
        const float wgt  = (w >= 0 && w < W_ && j >= 0) ? s * SCALE * gate : 0.f;
        if ((lane & 3) == 0) wsw[rr * 8 + myq] = wgt;
    }
    __syncwarp();

    // ---- Phase 2: each V row read ONCE; weights via broadcast LDS.128 ----
    float2 o[QPW];
#pragma unroll
    for (int i = 0; i < QPW; i++) o[i] = make_float2(0.f, 0.f);

#pragma unroll 4
    for (int rr = 0; rr < RPW; rr++) {
        const int l = qbase + rr;
        const float2 v2 = *(const float2*)(vs + l * STRIDE + 2 * lane);
        const float4 wa = *(const float4*)(wsw + rr * 8);
        const float4 wb = *(const float4*)(wsw + rr * 8 + 4);
        const float wv[8] = {wa.x, wa.y, wa.z, wa.w, wb.x, wb.y, wb.z, wb.w};
#pragma unroll
        for (int i = 0; i < QPW; i++) {
            o[i].x = fmaf(wv[i], v2.x, o[i].x);
            o[i].y = fmaf(wv[i], v2.y, o[i].y);
        }
    }

#pragma unroll
    for (int i = 0; i < QPW; i++) {
        *(float2*)(outg + headBase + (size_t)(s0 + qbase + i) * (H_ * D_) + 2 * lane) = o[i];
    }
}

extern "C" void kernel_launch(void* const* d_in, const int* in_sizes, int n_in,
                              void* d_out, int out_size)
{
    const float* q = (const float*)d_in[0];
    const float* k = (const float*)d_in[1];
    const float* v = (const float*)d_in[2];
    const float* a = (const float*)d_in[3];
    const float* b = (const float*)d_in[4];
    float* out = (float*)d_out;

    const size_t smem = (size_t)(2 * ROWS * STRIDE + ROWS + 1 + 8 * RPW * 8) * sizeof(float);
    cudaFuncSetAttribute(swa_gated2_kernel,
                         cudaFuncAttributeMaxDynamicSharedMemorySize, (int)smem);

    dim3 grid(S_ / TS, H_, B_);
    swa_gated2_kernel<<<grid, 256, smem>>>(q, k, v, a, b, out);
}

// round 4
// speedup vs baseline: 1.4169x; 1.3698x over previous
#include <cuda_runtime.h>
#include <cstdint>

// Sliding-window gated attention (W=32, D=64) via tf32 mma.sync (sm_100-compatible).
// Per block: (b, h, 128 queries). Per warp: 16 queries, 48-col score band.
//   S[16,48] = (Q*scale)[16,64] @ K[48,64]^T    (48 m16n8k8 MMAs)
//   Wt = S * sigmoid(a_l * b_q) * band_mask     (register epilogue -> smem)
//   O[16,64] = Wt[16,48] @ V[48,64]             (48 m16n8k8 MMAs)

constexpr int B_ = 2, S_ = 2048, H_ = 8, D_ = 64, W_ = 32;
constexpr int TS   = 128;          // queries per block
constexpr int ROWS = TS + 32;      // 160 staged k/v rows (l = j - (s0-31))
constexpr int STRIDE = 68;         // smem row stride (floats) for q/k/v
constexpr int WSTR = 52;           // per-warp weight tile stride
constexpr float SCALE = 0.125f;

constexpr int OFF_Q = 0;
constexpr int SZ_Q  = TS * STRIDE;              // 8704
constexpr int OFF_K = OFF_Q + SZ_Q;
constexpr int SZ_K  = ROWS * STRIDE;            // 10880
constexpr int OFF_V = OFF_K + SZ_K;
constexpr int OFF_A = OFF_V + SZ_K;             // ROWS floats
constexpr int OFF_W = OFF_A + ROWS;             // 8 warps * 16 * WSTR
constexpr int SMEM_FLOATS = OFF_W + 8 * 16 * WSTR;   // 37280 floats = 149120 B

__device__ __forceinline__ float f2tf32(float x) {
    uint32_t r; asm("cvt.rna.tf32.f32 %0, %1;" : "=r"(r) : "f"(x));
    return __uint_as_float(r);
}
__device__ __forceinline__ uint32_t bits(float x) { return __float_as_uint(x); }

__device__ __forceinline__ void mma_tf32(float* d,
                                         uint32_t a0, uint32_t a1, uint32_t a2, uint32_t a3,
                                         uint32_t b0, uint32_t b1) {
    asm volatile("mma.sync.aligned.m16n8k8.row.col.f32.tf32.tf32.f32 "
                 "{%0,%1,%2,%3}, {%4,%5,%6,%7}, {%8,%9}, {%0,%1,%2,%3};"
                 : "+f"(d[0]), "+f"(d[1]), "+f"(d[2]), "+f"(d[3])
                 : "r"(a0), "r"(a1), "r"(a2), "r"(a3), "r"(b0), "r"(b1));
}

__global__ __launch_bounds__(256, 1)
void swa_mma_kernel(const float* __restrict__ qg,
                    const float* __restrict__ kg,
                    const float* __restrict__ vg,
                    const float* __restrict__ ag,
                    const float* __restrict__ bg,
                    float* __restrict__ outg)
{
    extern __shared__ float sm[];
    float* qs   = sm + OFF_Q;
    float* ks   = sm + OFF_K;
    float* vs   = sm + OFF_V;
    float* a_sm = sm + OFF_A;

    const int s0  = blockIdx.x * TS;
    const int h   = blockIdx.y;
    const int bb  = blockIdx.z;
    const int tid = threadIdx.x;
    const size_t headBase = (size_t)bb * S_ * (H_ * D_) + (size_t)h * D_;

    // ---- Stage Q (scaled, tf32) ----
    for (int idx = tid; idx < TS * 16; idx += 256) {
        const int r = idx >> 4, c4 = (idx & 15) << 2;
        const float4 f = *(const float4*)(qg + headBase + (size_t)(s0 + r) * (H_ * D_) + c4);
        float* dst = qs + r * STRIDE + c4;
        dst[0] = f2tf32(f.x * SCALE); dst[1] = f2tf32(f.y * SCALE);
        dst[2] = f2tf32(f.z * SCALE); dst[3] = f2tf32(f.w * SCALE);
    }
    // ---- Stage K, V (tf32, zero-fill out-of-range rows) ----
    for (int idx = tid; idx < ROWS * 16; idx += 256) {
        const int r = idx >> 4, c4 = (idx & 15) << 2;
        const int j = s0 - (W_ - 1) + r;
        float4 fk = make_float4(0.f, 0.f, 0.f, 0.f), fv = fk;
        if (j >= 0 && j < S_) {
            const size_t off = headBase + (size_t)j * (H_ * D_) + c4;
            fk = *(const float4*)(kg + off);
            fv = *(const float4*)(vg + off);
        }
        float* dk = ks + r * STRIDE + c4;
        float* dv = vs + r * STRIDE + c4;
        dk[0] = f2tf32(fk.x); dk[1] = f2tf32(fk.y); dk[2] = f2tf32(fk.z); dk[3] = f2tf32(fk.w);
        dv[0] = f2tf32(fv.x); dv[1] = f2tf32(fv.y); dv[2] = f2tf32(fv.z); dv[3] = f2tf32(fv.w);
    }
    for (int r = tid; r < ROWS; r += 256) {
        const int j = s0 - (W_ - 1) + r;
        a_sm[r] = (j >= 0 && j < S_) ? ag[((size_t)bb * S_ + j) * H_ + h] : 0.f;
    }
    __syncthreads();

    const int warp = tid >> 5;
    const int lane = tid & 31;
    const int gid  = lane >> 2;      // group id (row within fragment)
    const int tig  = lane & 3;       // thread in group
    const int qb   = warp * 16;      // warp's first local query
    float* wsw = sm + OFF_W + warp * (16 * WSTR);

    const float bq0 = bg[((size_t)bb * S_ + (s0 + qb + gid)) * H_ + h];
    const float bq1 = bg[((size_t)bb * S_ + (s0 + qb + gid + 8)) * H_ + h];

    // ---- GEMM1: S[16,48] = Q @ K^T ----
    float acc[6][4] = {};
#pragma unroll
    for (int kk = 0; kk < 8; kk++) {
        const float* qrow = qs + (qb + gid) * STRIDE + kk * 8 + tig;
        const uint32_t a0 = bits(qrow[0]);
        const uint32_t a1 = bits(qrow[8 * STRIDE]);
        const uint32_t a2 = bits(qrow[4]);
        const uint32_t a3 = bits(qrow[8 * STRIDE + 4]);
#pragma unroll
        for (int nt = 0; nt < 6; nt++) {
            const float* kp = ks + (qb + nt * 8 + gid) * STRIDE + kk * 8 + tig;
            mma_tf32(acc[nt], a0, a1, a2, a3, bits(kp[0]), bits(kp[4]));
        }
    }

    // ---- Gating + band mask; write tf32 weights to per-warp smem tile ----
#pragma unroll
    for (int nt = 0; nt < 6; nt++) {
#pragma unroll
        for (int e = 0; e < 4; e++) {
            const int row = (e >= 2) ? gid + 8 : gid;           // row within 16-tile
            const int col = nt * 8 + 2 * tig + (e & 1);         // col within 48-band
            const int l   = qb + col;                           // block-local k row
            const int j   = s0 - (W_ - 1) + l;
            const int d   = col - row;
            const bool ok = (d >= 0) && (d < W_) && (j >= 0);
            const float bq = (e >= 2) ? bq1 : bq0;
            const float g = 1.f / (1.f + __expf(-a_sm[l] * bq));
            wsw[row * WSTR + col] = f2tf32(ok ? acc[nt][e] * g : 0.f);
        }
    }
    __syncwarp();

    // ---- GEMM2: O[16,64] = Wt[16,48] @ V[48,64] ----
    float oacc[8][4] = {};
#pragma unroll
    for (int kk = 0; kk < 6; kk++) {
        const float* wrow = wsw + gid * WSTR + kk * 8 + tig;
        const uint32_t a0 = bits(wrow[0]);
        const uint32_t a1 = bits(wrow[8 * WSTR]);
        const uint32_t a2 = bits(wrow[4]);
        const uint32_t a3 = bits(wrow[8 * WSTR + 4]);
#pragma unroll
        for (int nt = 0; nt < 8; nt++) {
            const float* vp0 = vs + (qb + kk * 8 + tig) * STRIDE + nt * 8 + gid;
            const float* vp1 = vp0 + 4 * STRIDE;
            mma_tf32(oacc[nt], a0, a1, a2, a3, bits(vp0[0]), bits(vp1[0]));
        }
    }

    // ---- Store O ----
    float* d0 = outg + headBase + (size_t)(s0 + qb + gid) * (H_ * D_) + 2 * tig;
    float* d1 = outg + headBase + (size_t)(s0 + qb + gid + 8) * (H_ * D_) + 2 * tig;
#pragma unroll
    for (int nt = 0; nt < 8; nt++) {
        *(float2*)(d0 + nt * 8) = make_float2(oacc[nt][0], oacc[nt][1]);
        *(float2*)(d1 + nt * 8) = make_float2(oacc[nt][2], oacc[nt][3]);
    }
}

extern "C" void kernel_launch(void* const* d_in, const int* in_sizes, int n_in,
                              void* d_out, int out_size)
{
    const float* q = (const float*)d_in[0];
    const float* k = (const float*)d_in[1];
    const float* v = (const float*)d_in[2];
    const float* a = (const float*)d_in[3];
    const float* b = (const float*)d_in[4];
    float* out = (float*)d_out;

    const int smem = SMEM_FLOATS * (int)sizeof(float);
    cudaFuncSetAttribute(swa_mma_kernel,
                         cudaFuncAttributeMaxDynamicSharedMemorySize, smem);
    dim3 grid(S_ / TS, H_, B_);
    swa_mma_kernel<<<grid, 256, smem>>>(q, k, v, a, b, out);
}

// round 5
// speedup vs baseline: 1.9942x; 1.4074x over previous
#include <cuda_runtime.h>
#include <cstdint>

// Sliding-window gated attention (W=32, D=64) via tf32 mma.sync (sm_100-compatible).
// Per block: (b, h, 128 queries). Per warp: 16 queries, 48-col score band.
//   S[16,48] = Q[16,64] @ K[48,64]^T            (48 m16n8k8 MMAs, Q frags from gmem)
//   Wt = S * SCALE * sigmoid(a_l * b_q) * mask  (register epilogue -> smem, aliased into K)
//   O[16,64] = Wt[16,48] @ V[48,64]             (48 m16n8k8 MMAs)

constexpr int B_ = 2, S_ = 2048, H_ = 8, D_ = 64, W_ = 32;
constexpr int HD = H_ * D_;
constexpr int TS   = 128;          // queries per block
constexpr int ROWS = TS + 32;      // 160 staged k/v rows
constexpr int STRIDE = 68;         // smem row stride (floats), conflict-free for GEMM1 B reads
constexpr int WSTR = 52;           // per-warp weight tile stride, conflict-free for GEMM2 A reads
constexpr float SCALE = 0.125f;

constexpr int OFF_K = 0;                        // 160*68 floats; aliased by W tiles after GEMM1
constexpr int SZ_K  = ROWS * STRIDE;            // 10880
constexpr int OFF_V = OFF_K + SZ_K;
constexpr int OFF_A = OFF_V + SZ_K;             // ROWS floats
constexpr int SMEM_FLOATS = OFF_A + ROWS;       // 21920 floats = 87680 B

__device__ __forceinline__ float f2tf32(float x) {
    uint32_t r; asm("cvt.rna.tf32.f32 %0, %1;" : "=r"(r) : "f"(x));
    return __uint_as_float(r);
}
__device__ __forceinline__ uint32_t bits(float x) { return __float_as_uint(x); }

__device__ __forceinline__ void mma_tf32(float* d,
                                         uint32_t a0, uint32_t a1, uint32_t a2, uint32_t a3,
                                         uint32_t b0, uint32_t b1) {
    asm volatile("mma.sync.aligned.m16n8k8.row.col.f32.tf32.tf32.f32 "
                 "{%0,%1,%2,%3}, {%4,%5,%6,%7}, {%8,%9}, {%0,%1,%2,%3};"
                 : "+f"(d[0]), "+f"(d[1]), "+f"(d[2]), "+f"(d[3])
                 : "r"(a0), "r"(a1), "r"(a2), "r"(a3), "r"(b0), "r"(b1));
}

__global__ __launch_bounds__(256, 2)
void swa_mma2_kernel(const float* __restrict__ qg,
                     const float* __restrict__ kg,
                     const float* __restrict__ vg,
                     const float* __restrict__ ag,
                     const float* __restrict__ bg,
                     float* __restrict__ outg)
{
    extern __shared__ float sm[];
    float* ks   = sm + OFF_K;
    float* vs   = sm + OFF_V;
    float* a_sm = sm + OFF_A;

    const int s0  = blockIdx.x * TS;
    const int h   = blockIdx.y;
    const int bb  = blockIdx.z;
    const int tid = threadIdx.x;
    const int warp = tid >> 5;
    const int lane = tid & 31;
    const int gid  = lane >> 2;      // fragment row-in-group
    const int tig  = lane & 3;       // thread in group
    const int qb   = warp * 16;      // warp's first local query
    const size_t headBase = (size_t)bb * S_ * HD + (size_t)h * D_;

    // ---- Q fragments straight from gmem (each element read once per warp) ----
    const float* qrow0 = qg + headBase + (size_t)(s0 + qb + gid) * HD;
    const float* qrow1 = qrow0 + (size_t)8 * HD;
    uint32_t qa[8][4];
#pragma unroll
    for (int kk = 0; kk < 8; kk++) {
        const int c = kk * 8 + tig;
        qa[kk][0] = bits(f2tf32(qrow0[c]));
        qa[kk][1] = bits(f2tf32(qrow1[c]));
        qa[kk][2] = bits(f2tf32(qrow0[c + 4]));
        qa[kk][3] = bits(f2tf32(qrow1[c + 4]));
    }
    const float bq0 = bg[((size_t)bb * S_ + (s0 + qb + gid)) * H_ + h];
    const float bq1 = bg[((size_t)bb * S_ + (s0 + qb + gid + 8)) * H_ + h];

    // ---- Stage K, V (tf32, zero-fill out-of-range rows) ----
    for (int idx = tid; idx < ROWS * 16; idx += 256) {
        const int r = idx >> 4, c4 = (idx & 15) << 2;
        const int j = s0 - (W_ - 1) + r;
        float4 fk = make_float4(0.f, 0.f, 0.f, 0.f), fv = fk;
        if (j >= 0 && j < S_) {
            const size_t off = headBase + (size_t)j * HD + c4;
            fk = *(const float4*)(kg + off);
            fv = *(const float4*)(vg + off);
        }
        float* dk = ks + r * STRIDE + c4;
        float* dv = vs + r * STRIDE + c4;
        dk[0] = f2tf32(fk.x); dk[1] = f2tf32(fk.y); dk[2] = f2tf32(fk.z); dk[3] = f2tf32(fk.w);
        dv[0] = f2tf32(fv.x); dv[1] = f2tf32(fv.y); dv[2] = f2tf32(fv.z); dv[3] = f2tf32(fv.w);
    }
    for (int r = tid; r < ROWS; r += 256) {
        const int j = s0 - (W_ - 1) + r;
        a_sm[r] = (j >= 0 && j < S_) ? ag[((size_t)bb * S_ + j) * H_ + h] : 0.f;
    }
    __syncthreads();

    // ---- GEMM1: S[16,48] = Q @ K^T ----
    float acc[6][4] = {};
#pragma unroll
    for (int kk = 0; kk < 8; kk++) {
#pragma unroll
        for (int nt = 0; nt < 6; nt++) {
            const float* kp = ks + (qb + nt * 8 + gid) * STRIDE + kk * 8 + tig;
            mma_tf32(acc[nt], qa[kk][0], qa[kk][1], qa[kk][2], qa[kk][3],
                     bits(kp[0]), bits(kp[4]));
        }
    }
    __syncthreads();   // all K reads done -> W tiles may overwrite K region

    // ---- Gating + band mask; weights (tf32) into per-warp tile aliased over K ----
    float* wsw = ks + warp * (16 * WSTR);
#pragma unroll
    for (int nt = 0; nt < 6; nt++) {
#pragma unroll
        for (int e = 0; e < 4; e++) {
            const int row = (e >= 2) ? gid + 8 : gid;
            const int col = nt * 8 + 2 * tig + (e & 1);
            const int l   = qb + col;
            const int j   = s0 - (W_ - 1) + l;
            const int d   = col - row;
            const bool ok = (d >= 0) && (d < W_) && (j >= 0);
            const float bq = (e >= 2) ? bq1 : bq0;
            const float g = 1.f / (1.f + __expf(-a_sm[l] * bq));
            wsw[row * WSTR + col] = f2tf32(ok ? acc[nt][e] * (SCALE * g) : 0.f);
        }
    }
    __syncwarp();

    // ---- GEMM2: O[16,64] = Wt[16,48] @ V[48,64] ----
    float oacc[8][4] = {};
#pragma unroll
    for (int kk = 0; kk < 6; kk++) {
        const float* wrow = wsw + gid * WSTR + kk * 8 + tig;
        const uint32_t a0 = bits(wrow[0]);
        const uint32_t a1 = bits(wrow[8 * WSTR]);
        const uint32_t a2 = bits(wrow[4]);
        const uint32_t a3 = bits(wrow[8 * WSTR + 4]);
#pragma unroll
        for (int nt = 0; nt < 8; nt++) {
            const float* vp0 = vs + (qb + kk * 8 + tig) * STRIDE + nt * 8 + gid;
            const float* vp1 = vp0 + 4 * STRIDE;
            mma_tf32(oacc[nt], a0, a1, a2, a3, bits(vp0[0]), bits(vp1[0]));
        }
    }

    // ---- Store O ----
    float* d0 = outg + headBase + (size_t)(s0 + qb + gid) * HD + 2 * tig;
    float* d1 = d0 + (size_t)8 * HD;
#pragma unroll
    for (int nt = 0; nt < 8; nt++) {
        *(float2*)(d0 + nt * 8) = make_float2(oacc[nt][0], oacc[nt][1]);
        *(float2*)(d1 + nt * 8) = make_float2(oacc[nt][2], oacc[nt][3]);
    }
}

extern "C" void kernel_launch(void* const* d_in, const int* in_sizes, int n_in,
                              void* d_out, int out_size)
{
    const float* q = (const float*)d_in[0];
    const float* k = (const float*)d_in[1];
    const float* v = (const float*)d_in[2];
    const float* a = (const float*)d_in[3];
    const float* b = (const float*)d_in[4];
    float* out = (float*)d_out;

    const int smem = SMEM_FLOATS * (int)sizeof(float);   // 87680 B -> 2 CTAs/SM
    cudaFuncSetAttribute(swa_mma2_kernel,
                         cudaFuncAttributeMaxDynamicSharedMemorySize, smem);
    dim3 grid(S_ / TS, H_, B_);
    swa_mma2_kernel<<<grid, 256, smem>>>(q, k, v, a, b, out);
}